// round 16
// baseline (speedup 1.0000x reference)
#include <cuda_runtime.h>
#include <cuda_fp16.h>
#include <math.h>
#include <stdint.h>

#define DIM    512
#define MAXN   32768
#define MAXNE  4096
#define MARGIN 4e-3f
#define BM 128

__device__ float g_inv_norm[MAXNE];
__device__ float g_scale[MAXNE];
__device__ int   g_ind[MAXN];
__device__ int   g_flag01[MAXN];
__device__ float g_diff;
__device__ int   g_nflag;
__device__ int   g_done;
__device__ int   g_flag[MAXN];
__device__ unsigned long long g_best[MAXN];

__device__ __forceinline__ uint32_t h2_bits(__half2 h) {
    uint32_t u;
    *(__half2*)&u = h;
    return u;
}
__device__ __forceinline__ uint32_t smem_u32(const void* p) {
    uint32_t a;
    asm("{ .reg .u64 t; cvta.to.shared.u64 t, %1; cvt.u32.u64 %0, t; }" : "=r"(a) : "l"(p));
    return a;
}
__device__ __forceinline__ void cpa16(uint32_t dst, const void* src) {
    asm volatile("cp.async.cg.shared.global [%0], [%1], 16;" :: "r"(dst), "l"(src) : "memory");
}
#define CPC()  asm volatile("cp.async.commit_group;" ::: "memory")
#define CPW(n) asm volatile("cp.async.wait_group %0;" :: "n"(n) : "memory")

__device__ __forceinline__ void ldsm4(uint32_t& a0, uint32_t& a1, uint32_t& a2, uint32_t& a3, uint32_t addr) {
    asm volatile("ldmatrix.sync.aligned.m8n8.x4.shared.b16 {%0,%1,%2,%3}, [%4];"
                 : "=r"(a0), "=r"(a1), "=r"(a2), "=r"(a3) : "r"(addr));
}
__device__ __forceinline__ void mma16816(float* c, const uint32_t* a, const uint32_t* b) {
    asm volatile("mma.sync.aligned.m16n8k16.row.col.f32.f16.f16.f32 "
                 "{%0,%1,%2,%3}, {%4,%5,%6,%7}, {%8,%9}, {%0,%1,%2,%3};"
                 : "+f"(c[0]), "+f"(c[1]), "+f"(c[2]), "+f"(c[3])
                 : "r"(a[0]), "r"(a[1]), "r"(a[2]), "r"(a[3]), "r"(b[0]), "r"(b[1]));
}
__device__ __forceinline__ void upd(float& b, float& s, int& i, float v, int col) {
    if (v > b) { s = b; b = v; i = col; } else if (v > s) s = v;
}
__device__ __forceinline__ void mrg(float& b, float& s, int& i, float ob, float os, int oi) {
    if (ob > b || (ob == b && oi < i)) { s = fmaxf(b, os); b = ob; i = oi; }
    else s = fmaxf(s, ob);
}
__device__ __forceinline__ unsigned long long pack_key(float m, int code) {
    uint32_t u = __float_as_uint(m);
    u = (u & 0x80000000u) ? ~u : (u | 0x80000000u);
    return ((unsigned long long)u << 32) | (0xFFFFFFFFu - (uint32_t)code);
}

// ---- K1: fused norms + w fp16 + w transpose + resets ----
__global__ void prep_w(const float* __restrict__ w, __half* __restrict__ wh,
                       float* __restrict__ wt, int ne) {
    int row = blockIdx.x;
    const float* wr = w + (size_t)row * DIM;
    float4 v = ((const float4*)wr)[threadIdx.x];
    float s = v.x*v.x + v.y*v.y + v.z*v.z + v.w*v.w;
    ((__half2*)(wh + (size_t)row * DIM))[threadIdx.x * 2]     = __floats2half2_rn(v.x, v.y);
    ((__half2*)(wh + (size_t)row * DIM))[threadIdx.x * 2 + 1] = __floats2half2_rn(v.z, v.w);
    int k = threadIdx.x * 4;
    wt[(size_t)k * ne + row] = v.x;
    wt[(size_t)(k + 1) * ne + row] = v.y;
    wt[(size_t)(k + 2) * ne + row] = v.z;
    wt[(size_t)(k + 3) * ne + row] = v.w;
    __shared__ float red[4];
    #pragma unroll
    for (int o = 16; o; o >>= 1) s += __shfl_down_sync(0xffffffffu, s, o);
    if ((threadIdx.x & 31) == 0) red[threadIdx.x >> 5] = s;
    __syncthreads();
    if (threadIdx.x == 0) {
        float t = red[0] + red[1] + red[2] + red[3];
        float nm = sqrtf(t);
        g_inv_norm[row] = 1.0f / nm;
        g_scale[row] = fminf(1.0f, 1.0f / fmaxf(nm, 1e-7f));
        if (row == 0) { g_diff = 0.f; g_nflag = 0; g_done = 0; }
    }
}

// ---- K2: HMMA GEMM + top-2 argmax, fragment-pipelined ----
// 512 thr = 16 warps (4M x 4N), warp tile 32x32, CTA tile 128 rows x 128 codes.
// A (x) fp32->fp16 in-kernel, persistent (128KB); B 3-stage pipeline (96KB).
__global__ __launch_bounds__(512, 1)
void gemm_argmax(const float* __restrict__ x, const __half* __restrict__ wh,
                 int n, int ne) {
    extern __shared__ char sm[];
    const uint32_t sb = smem_u32(sm);
    const uint32_t sbB = sb + 131072;
    const int tid = threadIdx.x, lane = tid & 31, wid = tid >> 5;
    const int wm = wid >> 2, wn = wid & 3;
    const int rowBase = blockIdx.x * BM;
    const int tiles = ne >> 7;
    const int nchunks = tiles * 4;

    auto issueB = [&](int h, int st) {
        const int ctb = h >> 2, kb = h & 3;
        #pragma unroll
        for (int i = 0; i < 4; ++i) {
            int idx = tid + i * 512;
            int sub = idx >> 10, rem = idx & 1023;
            int r = rem >> 3, c = rem & 7;
            uint32_t sw = (uint32_t)(sub * 16384 + r * 128 + ((c ^ (r & 7)) << 4));
            cpa16(sbB + st * 32768 + sw,
                  wh + (size_t)(ctb * 128 + r) * DIM + kb * 128 + sub * 64 + c * 8);
        }
        CPC();
    };

    issueB(0, 0);
    issueB(1, 1);

    // A fill: fp32 x -> fp16 smem, once.
    #pragma unroll
    for (int kb = 0; kb < 4; ++kb) {
        #pragma unroll
        for (int i = 0; i < 4; ++i) {
            int idx = tid + i * 512;
            int sub = idx >> 10, rem = idx & 1023;
            int r = rem >> 3, c = rem & 7;
            uint32_t sw = (uint32_t)(sub * 16384 + r * 128 + ((c ^ (r & 7)) << 4));
            int gr = rowBase + r; if (gr >= n) gr = n - 1;
            const float4* px = (const float4*)(x + (size_t)gr * DIM + kb * 128 + sub * 64 + c * 8);
            float4 v0 = __ldg(px);
            float4 v1 = __ldg(px + 1);
            uint4 hv;
            hv.x = h2_bits(__floats2half2_rn(v0.x, v0.y));
            hv.y = h2_bits(__floats2half2_rn(v0.z, v0.w));
            hv.z = h2_bits(__floats2half2_rn(v1.x, v1.y));
            hv.w = h2_bits(__floats2half2_rn(v1.z, v1.w));
            *(uint4*)(sm + (sw + kb * 32768)) = hv;
        }
    }

    float best[4], second[4];
    int bidx[4];
    #pragma unroll
    for (int s = 0; s < 4; ++s) { best[s] = -3.4e38f; second[s] = -3.4e38f; bidx[s] = 0; }

    float acc[2][4][4];
    #pragma unroll
    for (int mt = 0; mt < 2; ++mt)
        #pragma unroll
        for (int nt = 0; nt < 4; ++nt)
            #pragma unroll
            for (int k = 0; k < 4; ++k) acc[mt][nt][k] = 0.f;

    // fragment addresses for this thread (ks-dependent part added per step)
    const int arow0 = wm * 32 + (lane & 15);
    const int arow1 = arow0 + 16;
    const int akc = (lane >> 4);
    const int brow0 = wn * 32 + (lane & 7) + ((lane >> 4) << 3);
    const int brow1 = brow0 + 16;
    const int bkc = ((lane >> 3) & 1);

    for (int g = 0; g < nchunks; ++g) {
        if (g == nchunks - 1) { CPW(0); } else { CPW(1); }
        __syncthreads();
        if (g + 2 < nchunks) issueB(g + 2, (g + 2) % 3);

        const uint32_t ablk = sb + (g & 3) * 32768;
        const uint32_t bblk = sbB + (g % 3) * 32768;

        uint32_t afr[2][2][4], bfr[2][2][4];
        auto load_frag = [&](int ks, int buf) {
            const int sub = ks >> 2, ksl = ks & 3;
            const uint32_t abase = ablk + sub * 16384;
            const uint32_t bbase = bblk + sub * 16384;
            int kcA = ksl * 2 + akc;
            ldsm4(afr[buf][0][0], afr[buf][0][1], afr[buf][0][2], afr[buf][0][3],
                  abase + arow0 * 128 + ((kcA ^ (arow0 & 7)) << 4));
            ldsm4(afr[buf][1][0], afr[buf][1][1], afr[buf][1][2], afr[buf][1][3],
                  abase + arow1 * 128 + ((kcA ^ (arow1 & 7)) << 4));
            int kcB = ksl * 2 + bkc;
            ldsm4(bfr[buf][0][0], bfr[buf][0][1], bfr[buf][0][2], bfr[buf][0][3],
                  bbase + brow0 * 128 + ((kcB ^ (brow0 & 7)) << 4));
            ldsm4(bfr[buf][1][0], bfr[buf][1][1], bfr[buf][1][2], bfr[buf][1][3],
                  bbase + brow1 * 128 + ((kcB ^ (brow1 & 7)) << 4));
        };

        load_frag(0, 0);
        #pragma unroll
        for (int ks = 0; ks < 8; ++ks) {
            const int cur = ks & 1, nxt = cur ^ 1;
            if (ks < 7) load_frag(ks + 1, nxt);
            #pragma unroll
            for (int mt = 0; mt < 2; ++mt)
                #pragma unroll
                for (int nt = 0; nt < 4; ++nt)
                    mma16816(acc[mt][nt], afr[cur][mt], &bfr[cur][nt >> 1][(nt & 1) * 2]);
        }

        if ((g & 3) == 3) {
            const int ct = g >> 2;
            #pragma unroll
            for (int nt = 0; nt < 4; ++nt) {
                int col = ct * 128 + wn * 32 + nt * 8 + (lane & 3) * 2;
                float i0 = __ldg(&g_inv_norm[col]);
                float i1 = __ldg(&g_inv_norm[col + 1]);
                #pragma unroll
                for (int mt = 0; mt < 2; ++mt) {
                    int s0 = mt * 2, s1 = mt * 2 + 1;
                    upd(best[s0], second[s0], bidx[s0], acc[mt][nt][0] * i0, col);
                    upd(best[s0], second[s0], bidx[s0], acc[mt][nt][1] * i1, col + 1);
                    upd(best[s1], second[s1], bidx[s1], acc[mt][nt][2] * i0, col);
                    upd(best[s1], second[s1], bidx[s1], acc[mt][nt][3] * i1, col + 1);
                    acc[mt][nt][0] = 0.f; acc[mt][nt][1] = 0.f;
                    acc[mt][nt][2] = 0.f; acc[mt][nt][3] = 0.f;
                }
            }
        }
    }

    #pragma unroll
    for (int s = 0; s < 4; ++s) {
        #pragma unroll
        for (int d = 1; d <= 2; d <<= 1) {
            float ob = __shfl_xor_sync(0xffffffffu, best[s], d);
            float os = __shfl_xor_sync(0xffffffffu, second[s], d);
            int   oi = __shfl_xor_sync(0xffffffffu, bidx[s], d);
            mrg(best[s], second[s], bidx[s], ob, os, oi);
        }
    }

    __syncthreads();
    float* mb = (float*)sm;
    float* ms = mb + 512;
    int*   mi = (int*)(ms + 512);
    if ((lane & 3) == 0) {
        #pragma unroll
        for (int s = 0; s < 4; ++s) {
            int row = wm * 32 + (s >> 1) * 16 + (s & 1) * 8 + (lane >> 2);
            mb[wn * 128 + row] = best[s];
            ms[wn * 128 + row] = second[s];
            mi[wn * 128 + row] = bidx[s];
        }
    }
    __syncthreads();
    if (tid < 128) {
        float bb2 = mb[tid], ss2 = ms[tid];
        int bi = mi[tid];
        #pragma unroll
        for (int w = 1; w < 4; ++w)
            mrg(bb2, ss2, bi, mb[w * 128 + tid], ms[w * 128 + tid], mi[w * 128 + tid]);
        int grow = rowBase + tid;
        if (grow < n) {
            g_ind[grow] = bi;
            int fl = (bb2 - ss2 < MARGIN) ? 1 : 0;
            g_flag01[grow] = fl;
            if (fl) {
                int pos = atomicAdd(&g_nflag, 1);
                if (pos < MAXN) g_flag[pos] = grow;
                g_best[grow] = 0ull;
            }
        }
    }
}

// ---- K3: exact fp32 recheck: (16-row group) x (256-code slice) ----
__global__ __launch_bounds__(256, 1)
void recheck_kernel(const float* __restrict__ x, const float* __restrict__ wt, int ne) {
    __shared__ float xs[16][DIM];
    const int tid = threadIdx.x, lane = tid & 31;
    int nf = g_nflag; if (nf > MAXN) nf = MAXN;
    const int ngroups = (nf + 15) >> 4;
    const int nslice = ne >> 8;
    const int total = ngroups * nslice;

    for (int wk = blockIdx.x; wk < total; wk += gridDim.x) {
        const int grp = wk / nslice, slice = wk - grp * nslice;
        const int base = grp * 16;
        int cnt = nf - base; if (cnt > 16) cnt = 16;
        __syncthreads();
        for (int e = tid; e < cnt * DIM; e += 256) {
            int r = e >> 9, k = e & 511;
            xs[r][k] = x[(size_t)g_flag[base + r] * DIM + k];
        }
        __syncthreads();

        const int code = slice * 256 + tid;
        float acc[16];
        #pragma unroll
        for (int r = 0; r < 16; ++r) acc[r] = 0.f;

        for (int kq0 = 0; kq0 < DIM / 4; kq0 += 2) {
            float wv[8];
            #pragma unroll
            for (int u = 0; u < 2; ++u) {
                const float* wr = wt + (size_t)((kq0 + u) * 4) * ne + code;
                wv[u*4+0] = __ldg(wr);
                wv[u*4+1] = __ldg(wr + ne);
                wv[u*4+2] = __ldg(wr + 2 * ne);
                wv[u*4+3] = __ldg(wr + 3 * ne);
            }
            #pragma unroll
            for (int u = 0; u < 2; ++u) {
                #pragma unroll
                for (int r = 0; r < 16; ++r) {
                    float4 xv = *(const float4*)&xs[r][(kq0 + u) * 4];
                    acc[r] = fmaf(xv.x, wv[u*4],
                             fmaf(xv.y, wv[u*4+1],
                             fmaf(xv.z, wv[u*4+2],
                             fmaf(xv.w, wv[u*4+3], acc[r]))));
                }
            }
        }

        float inv = __ldg(&g_inv_norm[code]);
        #pragma unroll
        for (int r = 0; r < 16; ++r) {
            unsigned long long bk = pack_key(acc[r] * inv, code);
            #pragma unroll
            for (int o = 16; o; o >>= 1) {
                unsigned long long ok = __shfl_down_sync(0xffffffffu, bk, o);
                if (ok > bk) bk = ok;
            }
            if (lane == 0 && r < cnt)
                atomicMax(&g_best[g_flag[base + r]], bk);
        }
    }
}

// ---- K4: gather + MSE + fused finalize ----
__global__ void gather_kernel(const float* __restrict__ x, const float* __restrict__ w,
                              float* __restrict__ out0, float* __restrict__ out_ind,
                              float* __restrict__ diff_out, float inv_cnt,
                              int write_extra, int n) {
    const int warp = threadIdx.x >> 5, lane = threadIdx.x & 31;
    const int row = blockIdx.x * 8 + warp;
    float lsum = 0.f;
    if (row < n) {
        int ind = g_ind[row];
        if (g_flag01[row])
            ind = (int)(0xFFFFFFFFu - (uint32_t)(g_best[row] & 0xFFFFFFFFull));
        const float sc = g_scale[ind];
        const float4* px = (const float4*)(x + (size_t)row * DIM);
        const float4* pw = (const float4*)(w + (size_t)ind * DIM);
        float4* po = (float4*)(out0 + (size_t)row * DIM);
        #pragma unroll
        for (int it = 0; it < 4; ++it) {
            int idx = it * 32 + lane;
            float4 wv = pw[idx];
            float4 xv = __ldcs(px + idx);
            float4 q = make_float4(wv.x * sc, wv.y * sc, wv.z * sc, wv.w * sc);
            __stcs(po + idx, q);
            float dx = q.x - xv.x, dy = q.y - xv.y, dz = q.z - xv.z, dw = q.w - xv.w;
            lsum += dx * dx + dy * dy + dz * dz + dw * dw;
        }
        if (write_extra && lane == 0) out_ind[row] = (float)ind;
    }
    #pragma unroll
    for (int o = 16; o; o >>= 1) lsum += __shfl_down_sync(0xffffffffu, lsum, o);
    __shared__ float rs[8];
    if (lane == 0) rs[warp] = lsum;
    __syncthreads();
    if (threadIdx.x == 0) {
        float tt = 0.f;
        #pragma unroll
        for (int i = 0; i < 8; i++) tt += rs[i];
        atomicAdd(&g_diff, tt);
        __threadfence();
        int done = atomicAdd(&g_done, 1);
        if (write_extra && done == gridDim.x - 1)
            *diff_out = g_diff * inv_cnt;
    }
}

// ---- launch ----
extern "C" void kernel_launch(void* const* d_in, const int* in_sizes, int n_in,
                              void* d_out, int out_size) {
    const float* x = (const float*)d_in[0];
    const float* w = (const float*)d_in[1];
    int xe = in_sizes[0], we = (n_in >= 2) ? in_sizes[1] : 0;
    if (n_in >= 2 && we > xe) { const float* t = x; x = w; w = t; int te = xe; xe = we; we = te; }
    int n = xe / DIM, ne = we / DIM;
    if (n > MAXN) n = MAXN;
    if (ne > MAXNE) ne = MAXNE;
    float* out = (float*)d_out;
    const long long full = (long long)n * DIM + 1 + n;
    const int write_extra = (out_size >= full);

    __half* wh = (__half*)out;
    float*  wt = out + (size_t)ne * DIM / 2;

    cudaFuncSetAttribute(gemm_argmax, cudaFuncAttributeMaxDynamicSharedMemorySize, 229376);

    prep_w<<<ne, 128>>>(w, wh, wt, ne);
    gemm_argmax<<<(n + BM - 1) / BM, 512, 229376>>>(x, wh, n, ne);
    recheck_kernel<<<512, 256>>>(x, wt, ne);
    gather_kernel<<<(n + 7) / 8, 256>>>(x, w, out,
                                        write_extra ? out + (size_t)n * DIM + 1 : out,
                                        out + (size_t)n * DIM,
                                        1.0f / ((float)n * (float)DIM),
                                        write_extra, n);
}

// round 17
// speedup vs baseline: 1.0001x; 1.0001x over previous
#include <cuda_runtime.h>
#include <cuda_fp16.h>
#include <math.h>
#include <stdint.h>

#define DIM    512
#define MAXN   32768
#define MAXNE  4096
#define MARGIN 4e-3f
#define BM 128

__device__ float g_inv_norm[MAXNE];
__device__ float g_scale[MAXNE];
__device__ int   g_ind[MAXN];
__device__ int   g_flag01[MAXN];
__device__ float g_diff;
__device__ int   g_nflag;
__device__ int   g_done;
__device__ int   g_flag[MAXN];
__device__ unsigned long long g_best[MAXN];

__device__ __forceinline__ uint32_t h2_bits(__half2 h) {
    uint32_t u;
    *(__half2*)&u = h;
    return u;
}
__device__ __forceinline__ uint32_t smem_u32(const void* p) {
    uint32_t a;
    asm("{ .reg .u64 t; cvta.to.shared.u64 t, %1; cvt.u32.u64 %0, t; }" : "=r"(a) : "l"(p));
    return a;
}
__device__ __forceinline__ void cpa16(uint32_t dst, const void* src) {
    asm volatile("cp.async.cg.shared.global [%0], [%1], 16;" :: "r"(dst), "l"(src) : "memory");
}
#define CPC()  asm volatile("cp.async.commit_group;" ::: "memory")
#define CPW(n) asm volatile("cp.async.wait_group %0;" :: "n"(n) : "memory")

__device__ __forceinline__ void ldsm4(uint32_t& a0, uint32_t& a1, uint32_t& a2, uint32_t& a3, uint32_t addr) {
    asm volatile("ldmatrix.sync.aligned.m8n8.x4.shared.b16 {%0,%1,%2,%3}, [%4];"
                 : "=r"(a0), "=r"(a1), "=r"(a2), "=r"(a3) : "r"(addr));
}
__device__ __forceinline__ void mma16816(float* c, const uint32_t* a, const uint32_t* b) {
    asm volatile("mma.sync.aligned.m16n8k16.row.col.f32.f16.f16.f32 "
                 "{%0,%1,%2,%3}, {%4,%5,%6,%7}, {%8,%9}, {%0,%1,%2,%3};"
                 : "+f"(c[0]), "+f"(c[1]), "+f"(c[2]), "+f"(c[3])
                 : "r"(a[0]), "r"(a[1]), "r"(a[2]), "r"(a[3]), "r"(b[0]), "r"(b[1]));
}
__device__ __forceinline__ void upd(float& b, float& s, int& i, float v, int col) {
    if (v > b) { s = b; b = v; i = col; } else if (v > s) s = v;
}
__device__ __forceinline__ void mrg(float& b, float& s, int& i, float ob, float os, int oi) {
    if (ob > b || (ob == b && oi < i)) { s = fmaxf(b, os); b = ob; i = oi; }
    else s = fmaxf(s, ob);
}
__device__ __forceinline__ unsigned long long pack_key(float m, int code) {
    uint32_t u = __float_as_uint(m);
    u = (u & 0x80000000u) ? ~u : (u | 0x80000000u);
    return ((unsigned long long)u << 32) | (0xFFFFFFFFu - (uint32_t)code);
}

// ---- K1: fused norms + w fp16 + w transpose + resets ----
__global__ void prep_w(const float* __restrict__ w, __half* __restrict__ wh,
                       float* __restrict__ wt, int ne) {
    int row = blockIdx.x;
    const float* wr = w + (size_t)row * DIM;
    float4 v = ((const float4*)wr)[threadIdx.x];
    float s = v.x*v.x + v.y*v.y + v.z*v.z + v.w*v.w;
    ((__half2*)(wh + (size_t)row * DIM))[threadIdx.x * 2]     = __floats2half2_rn(v.x, v.y);
    ((__half2*)(wh + (size_t)row * DIM))[threadIdx.x * 2 + 1] = __floats2half2_rn(v.z, v.w);
    int k = threadIdx.x * 4;
    wt[(size_t)k * ne + row] = v.x;
    wt[(size_t)(k + 1) * ne + row] = v.y;
    wt[(size_t)(k + 2) * ne + row] = v.z;
    wt[(size_t)(k + 3) * ne + row] = v.w;
    __shared__ float red[4];
    #pragma unroll
    for (int o = 16; o; o >>= 1) s += __shfl_down_sync(0xffffffffu, s, o);
    if ((threadIdx.x & 31) == 0) red[threadIdx.x >> 5] = s;
    __syncthreads();
    if (threadIdx.x == 0) {
        float t = red[0] + red[1] + red[2] + red[3];
        float nm = sqrtf(t);
        g_inv_norm[row] = 1.0f / nm;
        g_scale[row] = fminf(1.0f, 1.0f / fmaxf(nm, 1e-7f));
        if (row == 0) { g_diff = 0.f; g_nflag = 0; g_done = 0; }
    }
}

// ---- K2: HMMA GEMM + top-2 argmax (round-15 configuration) ----
// 512 thr = 16 warps (4M x 4N), warp tile 32x32, CTA tile 128 rows x 128 codes.
// A (x) fp32->fp16 in-kernel, persistent (128KB); B 3-stage pipeline (96KB).
__global__ __launch_bounds__(512, 1)
void gemm_argmax(const float* __restrict__ x, const __half* __restrict__ wh,
                 int n, int ne) {
    extern __shared__ char sm[];
    const uint32_t sb = smem_u32(sm);
    const uint32_t sbB = sb + 131072;
    const int tid = threadIdx.x, lane = tid & 31, wid = tid >> 5;
    const int wm = wid >> 2, wn = wid & 3;
    const int rowBase = blockIdx.x * BM;
    const int tiles = ne >> 7;
    const int nchunks = tiles * 4;

    auto issueB = [&](int h, int st) {
        const int ctb = h >> 2, kb = h & 3;
        #pragma unroll
        for (int i = 0; i < 4; ++i) {
            int idx = tid + i * 512;
            int sub = idx >> 10, rem = idx & 1023;
            int r = rem >> 3, c = rem & 7;
            uint32_t sw = (uint32_t)(sub * 16384 + r * 128 + ((c ^ (r & 7)) << 4));
            cpa16(sbB + st * 32768 + sw,
                  wh + (size_t)(ctb * 128 + r) * DIM + kb * 128 + sub * 64 + c * 8);
        }
        CPC();
    };

    issueB(0, 0);
    issueB(1, 1);

    // A fill: fp32 x -> fp16 smem, once.
    #pragma unroll
    for (int kb = 0; kb < 4; ++kb) {
        #pragma unroll
        for (int i = 0; i < 4; ++i) {
            int idx = tid + i * 512;
            int sub = idx >> 10, rem = idx & 1023;
            int r = rem >> 3, c = rem & 7;
            uint32_t sw = (uint32_t)(sub * 16384 + r * 128 + ((c ^ (r & 7)) << 4));
            int gr = rowBase + r; if (gr >= n) gr = n - 1;
            const float4* px = (const float4*)(x + (size_t)gr * DIM + kb * 128 + sub * 64 + c * 8);
            float4 v0 = __ldg(px);
            float4 v1 = __ldg(px + 1);
            uint4 hv;
            hv.x = h2_bits(__floats2half2_rn(v0.x, v0.y));
            hv.y = h2_bits(__floats2half2_rn(v0.z, v0.w));
            hv.z = h2_bits(__floats2half2_rn(v1.x, v1.y));
            hv.w = h2_bits(__floats2half2_rn(v1.z, v1.w));
            *(uint4*)(sm + (sw + kb * 32768)) = hv;
        }
    }

    float best[4], second[4];
    int bidx[4];
    #pragma unroll
    for (int s = 0; s < 4; ++s) { best[s] = -3.4e38f; second[s] = -3.4e38f; bidx[s] = 0; }

    float acc[2][4][4];
    #pragma unroll
    for (int mt = 0; mt < 2; ++mt)
        #pragma unroll
        for (int nt = 0; nt < 4; ++nt)
            #pragma unroll
            for (int k = 0; k < 4; ++k) acc[mt][nt][k] = 0.f;

    for (int g = 0; g < nchunks; ++g) {
        if (g == nchunks - 1) { CPW(0); } else { CPW(1); }
        __syncthreads();
        if (g + 2 < nchunks) issueB(g + 2, (g + 2) % 3);

        const uint32_t ablk = sb + (g & 3) * 32768;
        const uint32_t bblk = sbB + (g % 3) * 32768;
        #pragma unroll
        for (int ks = 0; ks < 8; ++ks) {
            const int sub = ks >> 2, ksl = ks & 3;
            const uint32_t abase = ablk + sub * 16384;
            const uint32_t bbase = bblk + sub * 16384;
            uint32_t a[2][4];
            #pragma unroll
            for (int mt = 0; mt < 2; ++mt) {
                int ar = wm * 32 + mt * 16 + (lane & 15);
                int kc = ksl * 2 + (lane >> 4);
                ldsm4(a[mt][0], a[mt][1], a[mt][2], a[mt][3],
                      abase + ar * 128 + ((kc ^ (ar & 7)) << 4));
            }
            uint32_t bq[2][4];
            #pragma unroll
            for (int p = 0; p < 2; ++p) {
                int br = wn * 32 + p * 16 + (lane & 7) + ((lane >> 4) << 3);
                int kc = ksl * 2 + ((lane >> 3) & 1);
                ldsm4(bq[p][0], bq[p][1], bq[p][2], bq[p][3],
                      bbase + br * 128 + ((kc ^ (br & 7)) << 4));
            }
            #pragma unroll
            for (int mt = 0; mt < 2; ++mt)
                #pragma unroll
                for (int nt = 0; nt < 4; ++nt)
                    mma16816(acc[mt][nt], a[mt], &bq[nt >> 1][(nt & 1) * 2]);
        }

        if ((g & 3) == 3) {
            const int ct = g >> 2;
            #pragma unroll
            for (int nt = 0; nt < 4; ++nt) {
                int col = ct * 128 + wn * 32 + nt * 8 + (lane & 3) * 2;
                float i0 = __ldg(&g_inv_norm[col]);
                float i1 = __ldg(&g_inv_norm[col + 1]);
                #pragma unroll
                for (int mt = 0; mt < 2; ++mt) {
                    int s0 = mt * 2, s1 = mt * 2 + 1;
                    upd(best[s0], second[s0], bidx[s0], acc[mt][nt][0] * i0, col);
                    upd(best[s0], second[s0], bidx[s0], acc[mt][nt][1] * i1, col + 1);
                    upd(best[s1], second[s1], bidx[s1], acc[mt][nt][2] * i0, col);
                    upd(best[s1], second[s1], bidx[s1], acc[mt][nt][3] * i1, col + 1);
                    acc[mt][nt][0] = 0.f; acc[mt][nt][1] = 0.f;
                    acc[mt][nt][2] = 0.f; acc[mt][nt][3] = 0.f;
                }
            }
        }
    }

    #pragma unroll
    for (int s = 0; s < 4; ++s) {
        #pragma unroll
        for (int d = 1; d <= 2; d <<= 1) {
            float ob = __shfl_xor_sync(0xffffffffu, best[s], d);
            float os = __shfl_xor_sync(0xffffffffu, second[s], d);
            int   oi = __shfl_xor_sync(0xffffffffu, bidx[s], d);
            mrg(best[s], second[s], bidx[s], ob, os, oi);
        }
    }

    __syncthreads();
    float* mb = (float*)sm;
    float* ms = mb + 512;
    int*   mi = (int*)(ms + 512);
    if ((lane & 3) == 0) {
        #pragma unroll
        for (int s = 0; s < 4; ++s) {
            int row = wm * 32 + (s >> 1) * 16 + (s & 1) * 8 + (lane >> 2);
            mb[wn * 128 + row] = best[s];
            ms[wn * 128 + row] = second[s];
            mi[wn * 128 + row] = bidx[s];
        }
    }
    __syncthreads();
    if (tid < 128) {
        float bb2 = mb[tid], ss2 = ms[tid];
        int bi = mi[tid];
        #pragma unroll
        for (int w = 1; w < 4; ++w)
            mrg(bb2, ss2, bi, mb[w * 128 + tid], ms[w * 128 + tid], mi[w * 128 + tid]);
        int grow = rowBase + tid;
        if (grow < n) {
            g_ind[grow] = bi;
            int fl = (bb2 - ss2 < MARGIN) ? 1 : 0;
            g_flag01[grow] = fl;
            if (fl) {
                int pos = atomicAdd(&g_nflag, 1);
                if (pos < MAXN) g_flag[pos] = grow;
                g_best[grow] = 0ull;
            }
        }
    }
}

// ---- K3: exact fp32 recheck: (16-row group) x (256-code slice) ----
__global__ __launch_bounds__(256, 1)
void recheck_kernel(const float* __restrict__ x, const float* __restrict__ wt, int ne) {
    __shared__ float xs[16][DIM];
    const int tid = threadIdx.x, lane = tid & 31;
    int nf = g_nflag; if (nf > MAXN) nf = MAXN;
    const int ngroups = (nf + 15) >> 4;
    const int nslice = ne >> 8;
    const int total = ngroups * nslice;

    for (int wk = blockIdx.x; wk < total; wk += gridDim.x) {
        const int grp = wk / nslice, slice = wk - grp * nslice;
        const int base = grp * 16;
        int cnt = nf - base; if (cnt > 16) cnt = 16;
        __syncthreads();
        for (int e = tid; e < cnt * DIM; e += 256) {
            int r = e >> 9, k = e & 511;
            xs[r][k] = x[(size_t)g_flag[base + r] * DIM + k];
        }
        __syncthreads();

        const int code = slice * 256 + tid;
        float acc[16];
        #pragma unroll
        for (int r = 0; r < 16; ++r) acc[r] = 0.f;

        for (int kq0 = 0; kq0 < DIM / 4; kq0 += 2) {
            float wv[8];
            #pragma unroll
            for (int u = 0; u < 2; ++u) {
                const float* wr = wt + (size_t)((kq0 + u) * 4) * ne + code;
                wv[u*4+0] = __ldg(wr);
                wv[u*4+1] = __ldg(wr + ne);
                wv[u*4+2] = __ldg(wr + 2 * ne);
                wv[u*4+3] = __ldg(wr + 3 * ne);
            }
            #pragma unroll
            for (int u = 0; u < 2; ++u) {
                #pragma unroll
                for (int r = 0; r < 16; ++r) {
                    float4 xv = *(const float4*)&xs[r][(kq0 + u) * 4];
                    acc[r] = fmaf(xv.x, wv[u*4],
                             fmaf(xv.y, wv[u*4+1],
                             fmaf(xv.z, wv[u*4+2],
                             fmaf(xv.w, wv[u*4+3], acc[r]))));
                }
            }
        }

        float inv = __ldg(&g_inv_norm[code]);
        #pragma unroll
        for (int r = 0; r < 16; ++r) {
            unsigned long long bk = pack_key(acc[r] * inv, code);
            #pragma unroll
            for (int o = 16; o; o >>= 1) {
                unsigned long long ok = __shfl_down_sync(0xffffffffu, bk, o);
                if (ok > bk) bk = ok;
            }
            if (lane == 0 && r < cnt)
                atomicMax(&g_best[g_flag[base + r]], bk);
        }
    }
}

// ---- K4: gather + MSE + fused finalize ----
__global__ void gather_kernel(const float* __restrict__ x, const float* __restrict__ w,
                              float* __restrict__ out0, float* __restrict__ out_ind,
                              float* __restrict__ diff_out, float inv_cnt,
                              int write_extra, int n) {
    const int warp = threadIdx.x >> 5, lane = threadIdx.x & 31;
    const int row = blockIdx.x * 8 + warp;
    float lsum = 0.f;
    if (row < n) {
        int ind = g_ind[row];
        if (g_flag01[row])
            ind = (int)(0xFFFFFFFFu - (uint32_t)(g_best[row] & 0xFFFFFFFFull));
        const float sc = g_scale[ind];
        const float4* px = (const float4*)(x + (size_t)row * DIM);
        const float4* pw = (const float4*)(w + (size_t)ind * DIM);
        float4* po = (float4*)(out0 + (size_t)row * DIM);
        #pragma unroll
        for (int it = 0; it < 4; ++it) {
            int idx = it * 32 + lane;
            float4 wv = pw[idx];
            float4 xv = __ldcs(px + idx);
            float4 q = make_float4(wv.x * sc, wv.y * sc, wv.z * sc, wv.w * sc);
            __stcs(po + idx, q);
            float dx = q.x - xv.x, dy = q.y - xv.y, dz = q.z - xv.z, dw = q.w - xv.w;
            lsum += dx * dx + dy * dy + dz * dz + dw * dw;
        }
        if (write_extra && lane == 0) out_ind[row] = (float)ind;
    }
    #pragma unroll
    for (int o = 16; o; o >>= 1) lsum += __shfl_down_sync(0xffffffffu, lsum, o);
    __shared__ float rs[8];
    if (lane == 0) rs[warp] = lsum;
    __syncthreads();
    if (threadIdx.x == 0) {
        float tt = 0.f;
        #pragma unroll
        for (int i = 0; i < 8; i++) tt += rs[i];
        atomicAdd(&g_diff, tt);
        __threadfence();
        int done = atomicAdd(&g_done, 1);
        if (write_extra && done == gridDim.x - 1)
            *diff_out = g_diff * inv_cnt;
    }
}

// ---- launch ----
extern "C" void kernel_launch(void* const* d_in, const int* in_sizes, int n_in,
                              void* d_out, int out_size) {
    const float* x = (const float*)d_in[0];
    const float* w = (const float*)d_in[1];
    int xe = in_sizes[0], we = (n_in >= 2) ? in_sizes[1] : 0;
    if (n_in >= 2 && we > xe) { const float* t = x; x = w; w = t; int te = xe; xe = we; we = te; }
    int n = xe / DIM, ne = we / DIM;
    if (n > MAXN) n = MAXN;
    if (ne > MAXNE) ne = MAXNE;
    float* out = (float*)d_out;
    const long long full = (long long)n * DIM + 1 + n;
    const int write_extra = (out_size >= full);

    __half* wh = (__half*)out;
    float*  wt = out + (size_t)ne * DIM / 2;

    cudaFuncSetAttribute(gemm_argmax, cudaFuncAttributeMaxDynamicSharedMemorySize, 229376);

    prep_w<<<ne, 128>>>(w, wh, wt, ne);
    gemm_argmax<<<(n + BM - 1) / BM, 512, 229376>>>(x, wh, n, ne);
    recheck_kernel<<<512, 256>>>(x, wt, ne);
    gather_kernel<<<(n + 7) / 8, 256>>>(x, w, out,
                                        write_extra ? out + (size_t)n * DIM + 1 : out,
                                        out + (size_t)n * DIM,
                                        1.0f / ((float)n * (float)DIM),
                                        write_extra, n);
}